// round 17
// baseline (speedup 1.0000x reference)
#include <cuda_runtime.h>

#define NV 8192
#define NC 4096
#define NB 512
#define NE 24576
#define NITER 5
#define EPSF 1e-12f
// clip = float(1 - 1e-7) = 1 - 2^-23.  Image of [-clip, clip] under (1+x)/(1-x):
#define RMAXF 16777215.0f      // = 2^24 - 1
#define RMINF 5.9604648e-8f    // = 1/(2^24 - 1) rounded

#define TPB 1024               // threads per CTA; one CTA = TWO batch elements (float2)
#define VPT (NV / TPB)         // 8 vars / thread
#define CPT (NC / TPB)         // 4 checks / thread
// smem: st planes float2[3][NV] (192KB) + P float2[NC] (32KB) = 229376 B (opt-in)
#define SMEM_BYTES ((3 * NV + NC) * 8)

// Graph structure + caches (device globals: allocation-free per harness rules)
__device__ int    g_inv[NE];               // check -> 6 edge ids (atomic build order)
__device__ int    g_cnt[NC];               // build counters
__device__ uint4  g_inv8[NC];              // 6 u16 slotted-st offsets per check (edge-ascending)
__device__ uint2  g_chk4[NV];              // 3 u16 check ids per var
__device__ float4 g_vinfo[(NB / 2) * NV];  // per-CTA {c01, c2, Ex, Ey} records (32 MB)

// ---------------------------------------------------------------- index build
__global__ void zero_cnt() {
    int i = blockIdx.x * blockDim.x + threadIdx.x;
    if (i < NC) g_cnt[i] = 0;
}

__global__ void build_inv(const int* __restrict__ chk) {
    int e = blockIdx.x * blockDim.x + threadIdx.x;
    if (e < NE) {
        int c = chk[e];
        int s = atomicAdd(&g_cnt[c], 1);
        g_inv[c * 6 + s] = e;
    }
}

// Sort each check's 6 edges ascending (deterministic product order matching the
// reference's segment ops), map edge id -> plane-slotted st offset
// off(e) = (e%3)*NV + e/3, pack to u16. Also pack per-var check ids.
__global__ void pack_idx(const int* __restrict__ chk) {
    int i = blockIdx.x * blockDim.x + threadIdx.x;
    if (i < NC) {
        int a[6];
#pragma unroll
        for (int k = 0; k < 6; k++) a[k] = g_inv[i * 6 + k];
#pragma unroll
        for (int x = 1; x < 6; x++)
#pragma unroll
            for (int j = x; j > 0; j--)
                if (a[j] < a[j - 1]) { int t = a[j]; a[j] = a[j - 1]; a[j - 1] = t; }
        unsigned o[6];
#pragma unroll
        for (int k = 0; k < 6; k++) {
            int e = a[k];
            o[k] = (unsigned)((e % 3) * NV + (e / 3));
        }
        uint4 w;
        w.x = o[0] | (o[1] << 16);
        w.y = o[2] | (o[3] << 16);
        w.z = o[4] | (o[5] << 16);
        w.w = 0;
        g_inv8[i] = w;
    }
    if (i < NV) {
        uint2 w;
        w.x = (unsigned)chk[3 * i] | ((unsigned)chk[3 * i + 1] << 16);
        w.y = (unsigned)chk[3 * i + 2];
        g_chk4[i] = w;
    }
}

// ---------------------------------------------------------------- helpers
__device__ __forceinline__ float tanh_half_from_exp(float el) {
    float t = __fdividef(el - 1.0f, el + 1.0f);
    return t + copysignf(EPSF, t);
}

__device__ __forceinline__ float clamp_r(float r) {
    return fminf(fmaxf(r, RMINF), RMAXF);
}

__device__ __forceinline__ float2 r_pair(float2 st, float2 p) {
    float2 r;
    r.x = clamp_r(__fdividef(st.x + p.x, st.x - p.x));
    r.y = clamp_r(__fdividef(st.y + p.y, st.y - p.y));
    return r;
}

// ---------------------------------------------------------------- persistent per-batch-pair decoder
// One CTA decodes TWO batch elements entirely in shared memory (float2 lanes):
//   s_st[3*NV] : plane-slotted st — var v's edges at {v, NV+v, 2NV+v}
//   s_P[NC]    : per-check signed product of 6 st
// Loop-invariant tables held in registers (inv8) or fused 16B records (vinfo)
// so per-iteration l1tex traffic is only the unavoidable message accesses.
__global__ void __launch_bounds__(TPB, 1)
spa_kernel(const float* __restrict__ llr, float* __restrict__ out) {
    extern __shared__ float2 sm[];
    float2* s_st = sm;            // 3*NV float2
    float2* s_P  = sm + 3 * NV;   // NC float2

    int tid = threadIdx.x;
    int b0  = 2 * blockIdx.x;
    const float* llr0 = llr + (b0 + 0) * NV;
    const float* llr1 = llr + (b0 + 1) * NV;
    float4* vrow = g_vinfo + blockIdx.x * NV;

    // cache check-side gather offsets in registers for ALL iterations
    uint4 cwr[CPT];
#pragma unroll
    for (int m = 0; m < CPT; m++) cwr[m] = g_inv8[tid + m * TPB];

    // init: build vinfo {checks, E}, write iter-0 st on all 3 planes
#pragma unroll
    for (int m = 0; m < VPT; m++) {
        int v = tid + m * TPB;
        float Ex = __expf(llr0[v]);
        float Ey = __expf(llr1[v]);
        uint2 cw = g_chk4[v];
        float4 vi;
        vi.x = __uint_as_float(cw.x);
        vi.y = __uint_as_float(cw.y);
        vi.z = Ex;
        vi.w = Ey;
        vrow[v] = vi;
        float2 t;
        t.x = tanh_half_from_exp(Ex);
        t.y = tanh_half_from_exp(Ey);
        s_st[v]          = t;
        s_st[NV + v]     = t;
        s_st[2 * NV + v] = t;
    }
    __syncthreads();

    for (int it = 0; it < NITER; it++) {
        // ---- check phase: P[c] = signed product of 6 st (ascending edge order)
#pragma unroll
        for (int m = 0; m < CPT; m++) {
            int c = tid + m * TPB;
            uint4 w = cwr[m];
            float2 a0 = s_st[w.x & 0xFFFF];
            float2 a1 = s_st[w.x >> 16];
            float2 a2 = s_st[w.y & 0xFFFF];
            float2 a3 = s_st[w.y >> 16];
            float2 a4 = s_st[w.z & 0xFFFF];
            float2 a5 = s_st[w.z >> 16];
            float2 p;
            p.x = ((((a0.x * a1.x) * a2.x) * a3.x) * a4.x) * a5.x;
            p.y = ((((a0.y * a1.y) * a2.y) * a3.y) * a4.y) * a5.y;
            s_P[c] = p;
        }
        __syncthreads();

        // ---- var phase: out(it) + next-iteration st
        int ob0 = it * (NB * NV) + (b0 + 0) * NV;
        int ob1 = it * (NB * NV) + (b0 + 1) * NV;
#pragma unroll
        for (int m = 0; m < VPT; m++) {
            int v = tid + m * TPB;
            // one 16B record: packed check ids + exp(llr) pair
            float4 vi = vrow[v];
            unsigned cx = __float_as_uint(vi.x);
            unsigned cy = __float_as_uint(vi.y);
            // random P gathers first (longest-latency accesses)
            float2 p0 = s_P[cx & 0xFFFF];
            float2 p1 = s_P[cx >> 16];
            float2 p2 = s_P[cy];
            float2 st0 = s_st[v];
            float2 st1 = s_st[NV + v];
            float2 st2 = s_st[2 * NV + v];

            // r_e = e^{ext_e} = (st+P)/(st-P); signs cancel, r >= 0;
            // clamp is the exact image of the reference's loo clip.
            float2 r0 = r_pair(st0, p0);
            float2 r1 = r_pair(st1, p1);
            float2 r2 = r_pair(st2, p2);

            float r12x = r1.x * r2.x;
            float r12y = r1.y * r2.y;
            // out = llr + sum of ext = log(EL * r0*r1*r2)
            out[ob0 + v] = __logf(vi.z * (r0.x * r12x));
            out[ob1 + v] = __logf(vi.w * (r0.y * r12y));

            if (it < NITER - 1) {
                // e^{msg_e} = e^llr * product of the OTHER two r's
                float2 w0, w1, w2;
                w0.x = tanh_half_from_exp(vi.z * r12x);
                w0.y = tanh_half_from_exp(vi.w * r12y);
                w1.x = tanh_half_from_exp(vi.z * (r0.x * r2.x));
                w1.y = tanh_half_from_exp(vi.w * (r0.y * r2.y));
                w2.x = tanh_half_from_exp(vi.z * (r0.x * r1.x));
                w2.y = tanh_half_from_exp(vi.w * (r0.y * r1.y));
                s_st[v]          = w0;
                s_st[NV + v]     = w1;
                s_st[2 * NV + v] = w2;
            }
        }
        if (it < NITER - 1) __syncthreads();
    }
}

// ---------------------------------------------------------------- launch
extern "C" void kernel_launch(void* const* d_in, const int* in_sizes, int n_in,
                              void* d_out, int out_size) {
    const float* llr = (const float*)d_in[0];
    // d_in[1] = var_index: structured as repeat(arange(NV), 3) -> not needed
    const int* chk = (const int*)d_in[2];
    float* out = (float*)d_out;

    cudaFuncSetAttribute(spa_kernel, cudaFuncAttributeMaxDynamicSharedMemorySize,
                         SMEM_BYTES);

    zero_cnt<<<(NC + 255) / 256, 256>>>();
    build_inv<<<(NE + 255) / 256, 256>>>(chk);
    pack_idx<<<(NV + 255) / 256, 256>>>(chk);
    spa_kernel<<<NB / 2, TPB, SMEM_BYTES>>>(llr, out);
}